// round 11
// baseline (speedup 1.0000x reference)
#include <cuda_runtime.h>
#include <cuda_bf16.h>
#include <cuda_fp16.h>
#include <cstdint>

// Problem constants (AttentionPool: N=262144, D=512, H=128, B=1024)
#define MAXN 262144
#define MAXB 4096
#define DIM 512
#define HID 128

// ---------------------------------------------------------------------------
// Scratch (allocation-free rule: __device__ globals)
// ---------------------------------------------------------------------------
__device__ float g_scores[MAXN];
__device__ int   g_off[MAXB + 1];
// W1^T as fp16, layout [n][k]: n=0..127 rows, k=0..511 contiguous
__device__ __align__(16) unsigned short g_w1t[HID * DIM];
// x converted to fp16 by score kernel, row-major [N][D] (256 MB)
__device__ __align__(16) unsigned short g_xf16[(size_t)MAXN * DIM];

// ---------------------------------------------------------------------------
// Kernel 0 (fused prep):
//  blocks 0..3   : W1^T fp16 transpose via smem (coalesced both sides)
//  blocks 4..259 : segment offsets via boundary scatter over sorted batch
// ---------------------------------------------------------------------------
#define TPAD 132   // halfs per smem tile row

__global__ __launch_bounds__(256)
void prep_kernel(const void* __restrict__ batch, int n, int Bseg,
                 const float* __restrict__ W1)
{
    __shared__ unsigned short tile[128][TPAD];
    const int tid = threadIdx.x;

    if (blockIdx.x < 4) {
        const int k0 = blockIdx.x * 128;
#pragma unroll
        for (int u = 0; u < 16; u++) {
            int idx = tid + u * 256;
            int kr = idx >> 5;
            int c4 = idx & 31;
            float4 v = __ldg(reinterpret_cast<const float4*>(
                W1 + (size_t)(k0 + kr) * HID + c4 * 4));
            tile[c4 * 4 + 0][kr] = __half_as_ushort(__float2half_rn(v.x));
            tile[c4 * 4 + 1][kr] = __half_as_ushort(__float2half_rn(v.y));
            tile[c4 * 4 + 2][kr] = __half_as_ushort(__float2half_rn(v.z));
            tile[c4 * 4 + 3][kr] = __half_as_ushort(__float2half_rn(v.w));
        }
        __syncthreads();
#pragma unroll
        for (int u = 0; u < 8; u++) {
            int idx = tid + u * 256;
            int nn = idx >> 4;
            int c8 = idx & 15;
            unsigned short h[8];
#pragma unroll
            for (int j = 0; j < 8; j++) h[j] = tile[nn][c8 * 8 + j];
            *reinterpret_cast<uint4*>(g_w1t + (size_t)nn * DIM + k0 + c8 * 8) =
                *reinterpret_cast<const uint4*>(h);
        }
        return;
    }

    // --- segment offsets by boundary scatter (no dependent-load chains)
    const int gid = (blockIdx.x - 4) * 256 + tid;     // 65536 threads
    const int i32 = (__ldg((const int*)batch + (n - 1)) != 0);
    for (int i = gid; i < n; i += 65536) {
        long long bi, bp2;
        if (i32) {
            const int* a = (const int*)batch;
            bi = __ldg(a + i);
            bp2 = (i == 0) ? -1 : __ldg(a + i - 1);
        } else {
            const long long* a = (const long long*)batch;
            bi = __ldg(a + i);
            bp2 = (i == 0) ? -1 : __ldg(a + i - 1);
        }
        for (long long b = bp2 + 1; b <= bi; b++) g_off[b] = i;
        if (i == n - 1)
            for (long long b = bi + 1; b <= Bseg; b++) g_off[b] = n;
    }
}

// ---------------------------------------------------------------------------
// PTX helpers (all sm_80+ baseline -> safe for compute_103 target)
// ---------------------------------------------------------------------------
__device__ __forceinline__ void mma_f16(float* d, const uint32_t* a, const uint32_t* b)
{
    asm volatile(
        "mma.sync.aligned.m16n8k16.row.col.f32.f16.f16.f32 "
        "{%0,%1,%2,%3}, {%4,%5,%6,%7}, {%8,%9}, {%0,%1,%2,%3};"
        : "+f"(d[0]), "+f"(d[1]), "+f"(d[2]), "+f"(d[3])
        : "r"(a[0]), "r"(a[1]), "r"(a[2]), "r"(a[3]), "r"(b[0]), "r"(b[1]));
}
__device__ __forceinline__ void ldsm_x4(uint32_t* r, uint32_t addr)
{
    asm volatile("ldmatrix.sync.aligned.m8n8.x4.shared.b16 {%0,%1,%2,%3}, [%4];"
                 : "=r"(r[0]), "=r"(r[1]), "=r"(r[2]), "=r"(r[3]) : "r"(addr));
}
__device__ __forceinline__ void cp16(uint32_t dst, const void* src)
{
    asm volatile("cp.async.cg.shared.global [%0], [%1], 16;"
                 :: "r"(dst), "l"(src) : "memory");
}
__device__ __forceinline__ void cp_commit()
{
    asm volatile("cp.async.commit_group;" ::: "memory");
}
template <int N>
__device__ __forceinline__ void cp_wait()
{
    asm volatile("cp.async.wait_group %0;" :: "n"(N) : "memory");
}
__device__ __forceinline__ uint32_t smem_u32(const void* p)
{
    uint32_t a;
    asm("{ .reg .u64 t; cvta.to.shared.u64 t, %1; cvt.u32.u64 %0, t; }" : "=r"(a) : "l"(p));
    return a;
}

// ---------------------------------------------------------------------------
// Kernel 1: scores = tanh(x @ W1 + b1) @ W2 + b2  via single-pass fp16 mma.
// Side effect: writes x as fp16 to g_xf16 (consumed by pool kernel).
// Block: 64 rows x 128 cols (HID), 8 warps in 2x4 grid (warp tile 32x32).
// 3 CTAs/SM target (~85 regs). K loop: 8 tiles of 64, 144B-padded rows.
// B double-buffered via cp.async; A prefetched via batched LDGs.
// ---------------------------------------------------------------------------
#define KT       64
#define ROWPADB  144                      // bytes per smem row
#define TILE_A   (64 * ROWPADB)           // 9216 bytes (A fp16 tile)
#define TILE_B   (128 * ROWPADB)          // 18432 bytes per B buffer
#define OFF_A    0
#define OFF_B0   TILE_A
#define OFF_B1   (TILE_A + TILE_B)
#define SMEM_REQ (TILE_A + 2 * TILE_B)    // 46080 B

__global__ __launch_bounds__(256, 3)
void score_mma_kernel(const float* __restrict__ x,
                      const float* __restrict__ b1,
                      const float* __restrict__ W2,
                      const float* __restrict__ b2)
{
    extern __shared__ char bp[];
    const uint32_t sbase = smem_u32(bp);

    const int tid = threadIdx.x;
    const int wid = tid >> 5;
    const int lid = tid & 31;
    const int tig = lid & 3;             // 0..3
    const int warp_row = wid & 1;        // rows warp_row*32 ..
    const int warp_col = wid >> 1;       // cols warp_col*32 ..
    const int rowBase = blockIdx.x * 64;

    // ldmatrix per-lane addresses
    const uint32_t a_rl    = (uint32_t)(lid & 15);
    const uint32_t a_chalf = (uint32_t)((lid >> 4) * 16);
    uint32_t aA[2];
#pragma unroll
    for (int m = 0; m < 2; m++) {
        uint32_t row = (uint32_t)(warp_row * 32 + m * 16) + a_rl;
        aA[m] = sbase + OFF_A + row * ROWPADB + a_chalf;
    }
    const uint32_t b_lane = ((uint32_t)(lid & 7) + (uint32_t)((lid >> 4) & 1) * 8) * ROWPADB
                          + (uint32_t)((lid >> 3) & 1) * 16
                          + (uint32_t)warp_col * 32 * ROWPADB;

    float acc[2][4][4];
#pragma unroll
    for (int m = 0; m < 2; m++)
#pragma unroll
        for (int nt = 0; nt < 4; nt++)
#pragma unroll
            for (int j = 0; j < 4; j++) acc[m][nt][j] = 0.f;

    // --- prologue: B[0] via cp.async; A[0] LDGs into registers
    {
#pragma unroll
        for (int u = 0; u < 4; u++) {
            int idx = tid + u * 256;      // 1024 chunks of 16B
            int nn = idx >> 3, c8 = idx & 7;
            uint32_t doff = (uint32_t)nn * ROWPADB + (uint32_t)c8 * 16;
            uint32_t goff = (uint32_t)nn * DIM + (uint32_t)c8 * 8;  // t=0
            cp16(sbase + OFF_B0 + doff, g_w1t + goff);
        }
        cp_commit();
    }
    float4 va[4];                         // A: 512 chunks of 8 floats, 2/thread
#pragma unroll
    for (int u = 0; u < 2; u++) {
        int idx = tid + u * 256;
        int r = idx >> 3, c8 = idx & 7;
        const float4* src = reinterpret_cast<const float4*>(
            x + (size_t)(rowBase + r) * DIM + c8 * 8);
        va[2 * u]     = __ldg(src);
        va[2 * u + 1] = __ldg(src + 1);
    }

    for (int t = 0; t < 8; t++) {
        if (t > 0) __syncthreads();      // prior tile reads done before overwrite

        // --- convert prefetched A (fp32 -> fp16): store to smem + gmem side copy
#pragma unroll
        for (int u = 0; u < 2; u++) {
            int idx = tid + u * 256;
            int r = idx >> 3, c8 = idx & 7;
            float f[8] = {va[2 * u].x, va[2 * u].y, va[2 * u].z, va[2 * u].w,
                          va[2 * u + 1].x, va[2 * u + 1].y, va[2 * u + 1].z, va[2 * u + 1].w};
            uint32_t hp[4];
#pragma unroll
            for (int j = 0; j < 4; j++) {
                __half h0 = __float2half_rn(f[2 * j]);
                __half h1 = __float2half_rn(f[2 * j + 1]);
                hp[j] = (uint32_t)__half_as_ushort(h0) | ((uint32_t)__half_as_ushort(h1) << 16);
            }
            uint32_t off = (uint32_t)r * ROWPADB + (uint32_t)c8 * 16;
            uint4 v = make_uint4(hp[0], hp[1], hp[2], hp[3]);
            *(uint4*)(bp + OFF_A + off) = v;
            *reinterpret_cast<uint4*>(g_xf16 +
                (size_t)(rowBase + r) * DIM + t * KT + c8 * 8) = v;
        }

        // --- issue B[t+1] cp.async into alternate buffer, wait for B[t]
        if (t < 7) {
            uint32_t bufo = ((t + 1) & 1) ? OFF_B1 : OFF_B0;
#pragma unroll
            for (int u = 0; u < 4; u++) {
                int idx = tid + u * 256;
                int nn = idx >> 3, c8 = idx & 7;
                uint32_t doff = (uint32_t)nn * ROWPADB + (uint32_t)c8 * 16;
                uint32_t goff = (uint32_t)nn * DIM + (uint32_t)(t + 1) * KT + (uint32_t)c8 * 8;
                cp16(sbase + bufo + doff, g_w1t + goff);
            }
            cp_commit();
            cp_wait<1>();                 // B[t] complete; B[t+1] may stay in flight
        } else {
            cp_wait<0>();
        }
        __syncthreads();

        // --- prefetch next A tile LDGs (latency hidden behind compute below)
        if (t < 7) {
#pragma unroll
            for (int u = 0; u < 2; u++) {
                int idx = tid + u * 256;
                int r = idx >> 3, c8 = idx & 7;
                const float4* src = reinterpret_cast<const float4*>(
                    x + (size_t)(rowBase + r) * DIM + (t + 1) * KT + c8 * 8);
                va[2 * u]     = __ldg(src);
                va[2 * u + 1] = __ldg(src + 1);
            }
        }

        // --- compute: 4 k-steps of 16, single pass
        const uint32_t bA = sbase + ((t & 1) ? OFF_B1 : OFF_B0) + b_lane;
#pragma unroll
        for (int ks = 0; ks < 4; ks++) {
            const uint32_t ko = (uint32_t)ks * 32;
            uint32_t a[2][4];
#pragma unroll
            for (int m = 0; m < 2; m++) ldsm_x4(a[m], aA[m] + ko);
#pragma unroll
            for (int ntp = 0; ntp < 2; ntp++) {
                const uint32_t no = (uint32_t)ntp * 16 * ROWPADB + ko;
                uint32_t bh[4];
                ldsm_x4(bh, bA + no);
#pragma unroll
                for (int m = 0; m < 2; m++) {
                    mma_f16(acc[m][2 * ntp],     a[m], bh);
                    mma_f16(acc[m][2 * ntp + 1], a[m], bh + 2);
                }
            }
        }
    }

    // --- epilogue: s = sum_col tanh(h + b1[col]) * W2[col], register-resident
    const int grp = lid >> 2;
    float p[2][2] = {{0.f, 0.f}, {0.f, 0.f}};
#pragma unroll
    for (int nt = 0; nt < 4; nt++) {
        int c0 = warp_col * 32 + nt * 8 + tig * 2;
        float b1a = __ldg(b1 + c0),     b1b = __ldg(b1 + c0 + 1);
        float w2a = __ldg(W2 + c0),     w2b = __ldg(W2 + c0 + 1);
#pragma unroll
        for (int m = 0; m < 2; m++) {
            p[m][0] += tanhf(acc[m][nt][0] + b1a) * w2a + tanhf(acc[m][nt][1] + b1b) * w2b;
            p[m][1] += tanhf(acc[m][nt][2] + b1a) * w2a + tanhf(acc[m][nt][3] + b1b) * w2b;
        }
    }
#pragma unroll
    for (int m = 0; m < 2; m++)
#pragma unroll
        for (int r = 0; r < 2; r++) {
            p[m][r] += __shfl_xor_sync(0xFFFFFFFF, p[m][r], 1);
            p[m][r] += __shfl_xor_sync(0xFFFFFFFF, p[m][r], 2);
        }

    __syncthreads();                     // tiles no longer needed; reuse smem
    float* red = (float*)bp;             // [64][4]
    if (tig == 0) {
#pragma unroll
        for (int m = 0; m < 2; m++)
#pragma unroll
            for (int r = 0; r < 2; r++) {
                int row = warp_row * 32 + m * 16 + r * 8 + grp;
                red[row * 4 + warp_col] = p[m][r];
            }
    }
    __syncthreads();
    if (tid < 64)
        g_scores[rowBase + tid] = red[tid * 4] + red[tid * 4 + 1]
                                + red[tid * 4 + 2] + red[tid * 4 + 3] + __ldg(b2);
}

// ---------------------------------------------------------------------------
// Kernel 2 (fused softmax + pool): 2048 blocks = 1024 segments x 2 column
// halves. Per-segment softmax recomputed per block (scores L2-resident).
// out[b, ch*256 : (ch+1)*256) = sum_i w_i * x_f16[i, ...]
// 256 threads = 8 row-eighths (q) x 32 column chunks (t, 8 halfs = 16B).
// ---------------------------------------------------------------------------
__global__ __launch_bounds__(256)
void pool_softmax_kernel(float* __restrict__ out)
{
    const int b = blockIdx.x >> 1;
    const int ch = blockIdx.x & 1;       // column half
    const int tid = threadIdx.x;
    const int q = tid >> 5;              // 0..7 row eighth
    const int t = tid & 31;              // column chunk within half
    const int tcol = ch * 32 + t;        // global column chunk
    __shared__ float red[256];
    __shared__ float sh[7][32][8];       // partials from eighths 1..7

    const int lo = g_off[b];
    const int hi = g_off[b + 1];

    // --- segment max
    float m = -3.402823466e38f;
    for (int i = lo + tid; i < hi; i += 256) m = fmaxf(m, g_scores[i]);
    red[tid] = m;
    __syncthreads();
    for (int s = 128; s > 0; s >>= 1) {
        if (tid < s) red[tid] = fmaxf(red[tid], red[tid + s]);
        __syncthreads();
    }
    const float mm = red[0];
    __syncthreads();

    // --- sum of exp
    float sum = 0.f;
    for (int i = lo + tid; i < hi; i += 256) sum += expf(g_scores[i] - mm);
    red[tid] = sum;
    __syncthreads();
    for (int s = 128; s > 0; s >>= 1) {
        if (tid < s) red[tid] += red[tid + s];
        __syncthreads();
    }
    const float inv = 1.f / (red[0] + 1e-8f);

    // --- weighted sum over this eighth's rows (unroll 4 for MLP)
    const int len = hi - lo;
    const int s0 = lo + (int)(((long long)len * q) >> 3);
    const int e0 = lo + (int)(((long long)len * (q + 1)) >> 3);

    const uint4* xv = reinterpret_cast<const uint4*>(g_xf16) + tcol;
    float a[8];
#pragma unroll
    for (int j = 0; j < 8; j++) a[j] = 0.f;

    int i = s0;
    for (; i + 4 <= e0; i += 4) {
        float s0v = __ldg(g_scores + i);
        float s1v = __ldg(g_scores + i + 1);
        float s2v = __ldg(g_scores + i + 2);
        float s3v = __ldg(g_scores + i + 3);
        uint4 v0 = __ldg(xv + (size_t)(i + 0) * (DIM / 8));
        uint4 v1 = __ldg(xv + (size_t)(i + 1) * (DIM / 8));
        uint4 v2 = __ldg(xv + (size_t)(i + 2) * (DIM / 8));
        uint4 v3 = __ldg(xv + (size_t)(i + 3) * (DIM / 8));
        float w0 = expf(s0v - mm) * inv;
        float w1 = expf(s1v - mm) * inv;
        float w2 = expf(s2v - mm) * inv;
        float w3 = expf(s3v - mm) * inv;
        const uint32_t* u0 = &v0.x;
        const uint32_t* u1 = &v1.x;
        const uint32_t* u2 = &v2.x;
        const uint32_t* u3 = &v3.x;
#pragma unroll
        for (int j = 0; j < 4; j++) {
            float2 f0 = __half22float2(*reinterpret_cast<const __half2*>(&u0[j]));
            float2 f1 = __half22float2(*reinterpret_cast<const __half2*>(&u1[j]));
            float2 f2 = __half22float2(*reinterpret_cast<const __half2*>(&u2[j]));
            float2 f3 = __half22float2(*reinterpret_cast<const __half2*>(&u3[j]));
            a[2 * j]     += w0 * f0.x + w1 * f1.x + w2 * f2.x + w3 * f3.x;
            a[2 * j + 1] += w0 * f0.y + w1 * f1.y + w2 * f2.y + w3 * f3.y;
        }
    }
    for (; i < e0; i++) {
        float w = expf(__ldg(g_scores + i) - mm) * inv;
        uint4 v = __ldg(xv + (size_t)i * (DIM / 8));
        const uint32_t* u = &v.x;
#pragma unroll
        for (int j = 0; j < 4; j++) {
            float2 f = __half22float2(*reinterpret_cast<const __half2*>(&u[j]));
            a[2 * j]     += w * f.x;
            a[2 * j + 1] += w * f.y;
        }
    }

    if (q > 0) {
#pragma unroll
        for (int j = 0; j < 8; j++) sh[q - 1][t][j] = a[j];
    }
    __syncthreads();
    if (q == 0) {
#pragma unroll
        for (int e = 0; e < 7; e++)
#pragma unroll
            for (int j = 0; j < 8; j++) a[j] += sh[e][t][j];
        float4* o = reinterpret_cast<float4*>(out + (size_t)b * DIM + tcol * 8);
        o[0] = make_float4(a[0], a[1], a[2], a[3]);
        o[1] = make_float4(a[4], a[5], a[6], a[7]);
    }
}

// ---------------------------------------------------------------------------
extern "C" void kernel_launch(void* const* d_in, const int* in_sizes, int n_in,
                              void* d_out, int out_size)
{
    const float* x     = (const float*)d_in[0];
    const void*  batch = (const void*)d_in[1];
    const float* W1    = (const float*)d_in[2];
    const float* b1    = (const float*)d_in[3];
    const float* W2    = (const float*)d_in[4];
    const float* b2    = (const float*)d_in[5];
    float*       out   = (float*)d_out;

    const int n = in_sizes[1];
    const int Bseg = out_size / DIM;

    cudaFuncSetAttribute(score_mma_kernel,
                         cudaFuncAttributeMaxDynamicSharedMemorySize, SMEM_REQ);

    prep_kernel<<<4 + 256, 256>>>(batch, n, Bseg, W1);
    score_mma_kernel<<<n / 64, 256, SMEM_REQ>>>(x, b1, W2, b2);
    pool_softmax_kernel<<<2 * Bseg, 256>>>(out);
}

// round 12
// speedup vs baseline: 1.0162x; 1.0162x over previous
#include <cuda_runtime.h>
#include <cuda_bf16.h>
#include <cuda_fp16.h>
#include <cstdint>

// Problem constants (AttentionPool: N=262144, D=512, H=128, B=1024)
#define MAXN 262144
#define MAXB 4096
#define DIM 512
#define HID 128

// ---------------------------------------------------------------------------
// Scratch (allocation-free rule: __device__ globals)
// ---------------------------------------------------------------------------
__device__ __align__(16) float g_num[(size_t)MAXB * DIM];   // 8 MB
__device__ float g_den[MAXB];
// W1^T as fp16, layout [n][k]: n=0..127 rows, k=0..511 contiguous
__device__ __align__(16) unsigned short g_w1t[HID * DIM];

// ---------------------------------------------------------------------------
// Kernel 0 (fused prep):
//  blocks 0..3  : W1^T fp16 transpose via smem (coalesced both sides)
//  blocks 4..131: zero g_num[0..Bseg*DIM) and g_den[0..Bseg)
// ---------------------------------------------------------------------------
#define TPAD 132   // halfs per smem tile row
#define ZBLK 128

__global__ __launch_bounds__(256)
void prep_kernel(int Bseg, const float* __restrict__ W1)
{
    __shared__ unsigned short tile[128][TPAD];
    const int tid = threadIdx.x;

    if (blockIdx.x < 4) {
        const int k0 = blockIdx.x * 128;
#pragma unroll
        for (int u = 0; u < 16; u++) {
            int idx = tid + u * 256;
            int kr = idx >> 5;
            int c4 = idx & 31;
            float4 v = __ldg(reinterpret_cast<const float4*>(
                W1 + (size_t)(k0 + kr) * HID + c4 * 4));
            tile[c4 * 4 + 0][kr] = __half_as_ushort(__float2half_rn(v.x));
            tile[c4 * 4 + 1][kr] = __half_as_ushort(__float2half_rn(v.y));
            tile[c4 * 4 + 2][kr] = __half_as_ushort(__float2half_rn(v.z));
            tile[c4 * 4 + 3][kr] = __half_as_ushort(__float2half_rn(v.w));
        }
        __syncthreads();
#pragma unroll
        for (int u = 0; u < 8; u++) {
            int idx = tid + u * 256;
            int nn = idx >> 4;
            int c8 = idx & 15;
            unsigned short h[8];
#pragma unroll
            for (int j = 0; j < 8; j++) h[j] = tile[nn][c8 * 8 + j];
            *reinterpret_cast<uint4*>(g_w1t + (size_t)nn * DIM + k0 + c8 * 8) =
                *reinterpret_cast<const uint4*>(h);
        }
        return;
    }

    // --- zero accumulators
    const int gid = (blockIdx.x - 4) * 256 + tid;     // ZBLK*256 threads
    const int tot4 = Bseg * (DIM / 4);                // float4 count
    const uint4 z = make_uint4(0, 0, 0, 0);
    for (int i = gid; i < tot4; i += ZBLK * 256)
        reinterpret_cast<uint4*>(g_num)[i] = z;
    if (gid < Bseg) g_den[gid] = 0.f;
}

// ---------------------------------------------------------------------------
// PTX helpers (all sm_80+ baseline -> safe for compute_103 target)
// ---------------------------------------------------------------------------
__device__ __forceinline__ void mma_f16(float* d, const uint32_t* a, const uint32_t* b)
{
    asm volatile(
        "mma.sync.aligned.m16n8k16.row.col.f32.f16.f16.f32 "
        "{%0,%1,%2,%3}, {%4,%5,%6,%7}, {%8,%9}, {%0,%1,%2,%3};"
        : "+f"(d[0]), "+f"(d[1]), "+f"(d[2]), "+f"(d[3])
        : "r"(a[0]), "r"(a[1]), "r"(a[2]), "r"(a[3]), "r"(b[0]), "r"(b[1]));
}
__device__ __forceinline__ void ldsm_x4(uint32_t* r, uint32_t addr)
{
    asm volatile("ldmatrix.sync.aligned.m8n8.x4.shared.b16 {%0,%1,%2,%3}, [%4];"
                 : "=r"(r[0]), "=r"(r[1]), "=r"(r[2]), "=r"(r[3]) : "r"(addr));
}
__device__ __forceinline__ void cp16(uint32_t dst, const void* src)
{
    asm volatile("cp.async.cg.shared.global [%0], [%1], 16;"
                 :: "r"(dst), "l"(src) : "memory");
}
__device__ __forceinline__ void cp_commit()
{
    asm volatile("cp.async.commit_group;" ::: "memory");
}
template <int N>
__device__ __forceinline__ void cp_wait()
{
    asm volatile("cp.async.wait_group %0;" :: "n"(N) : "memory");
}
__device__ __forceinline__ uint32_t smem_u32(const void* p)
{
    uint32_t a;
    asm("{ .reg .u64 t; cvta.to.shared.u64 t, %1; cvt.u32.u64 %0, t; }" : "=r"(a) : "l"(p));
    return a;
}

// ---------------------------------------------------------------------------
// Kernel 1 (fused score + scatter-pool): per 64-row block,
//   s = tanh(x @ W1 + b1) @ W2 + b2     (single-pass fp16 mma)
//   then num[seg] += exp(s_i) * x_i,  den[seg] += exp(s_i)   via atomics,
// with x kept fully resident in smem as fp16 (read from DRAM exactly once).
// A rows padded to 1040B (1040 = 144 mod 128 -> same conflict-free pattern).
// ---------------------------------------------------------------------------
#define KT       64
#define ROWA     1040                     // bytes per full A row (512 fp16 + pad)
#define ROWPADB  144                      // bytes per B smem row
#define A_BYTES  (64 * ROWA)              // 66560
#define TILE_B   (128 * ROWPADB)          // 18432 per B buffer
#define OFF_A    0
#define OFF_B0   A_BYTES
#define OFF_B1   (A_BYTES + TILE_B)
#define OFF_TAIL (A_BYTES + 2 * TILE_B)   // 103424
// tail: seg[64] ints | e[64] floats | red[64*4] floats
#define OFF_SEG  OFF_TAIL
#define OFF_E    (OFF_TAIL + 256)
#define OFF_RED  (OFF_TAIL + 512)
#define SMEM_REQ (OFF_TAIL + 1536)        // 104960

__global__ __launch_bounds__(256, 2)
void score_pool_kernel(const float* __restrict__ x,
                       const void* __restrict__ batch, int n,
                       const float* __restrict__ b1,
                       const float* __restrict__ W2,
                       const float* __restrict__ b2)
{
    extern __shared__ char bp[];
    const uint32_t sbase = smem_u32(bp);

    const int tid = threadIdx.x;
    const int wid = tid >> 5;
    const int lid = tid & 31;
    const int tig = lid & 3;
    const int warp_row = wid & 1;        // rows warp_row*32 ..
    const int warp_col = wid >> 1;       // cols warp_col*32 ..
    const int rowBase = blockIdx.x * 64;

    int* seg_sm = (int*)(bp + OFF_SEG);
    float* e_sm = (float*)(bp + OFF_E);
    float* red  = (float*)(bp + OFF_RED);

    // --- load segment ids for this block's rows
    if (tid < 64) {
        const int i32 = (__ldg((const int*)batch + (n - 1)) != 0);
        seg_sm[tid] = i32 ? __ldg((const int*)batch + rowBase + tid)
                          : (int)__ldg((const long long*)batch + rowBase + tid);
    }

    // ldmatrix per-lane addresses
    const uint32_t a_rl    = (uint32_t)(lid & 15);
    const uint32_t a_chalf = (uint32_t)((lid >> 4) * 16);
    uint32_t aA[2];
#pragma unroll
    for (int m = 0; m < 2; m++) {
        uint32_t row = (uint32_t)(warp_row * 32 + m * 16) + a_rl;
        aA[m] = sbase + OFF_A + row * ROWA + a_chalf;
    }
    const uint32_t b_lane = ((uint32_t)(lid & 7) + (uint32_t)((lid >> 4) & 1) * 8) * ROWPADB
                          + (uint32_t)((lid >> 3) & 1) * 16
                          + (uint32_t)warp_col * 32 * ROWPADB;

    float acc[2][4][4];
#pragma unroll
    for (int m = 0; m < 2; m++)
#pragma unroll
        for (int nt = 0; nt < 4; nt++)
#pragma unroll
            for (int j = 0; j < 4; j++) acc[m][nt][j] = 0.f;

    // --- prologue: B[0] via cp.async; A[0] LDGs into registers
    {
#pragma unroll
        for (int u = 0; u < 4; u++) {
            int idx = tid + u * 256;      // 1024 chunks of 16B
            int nn = idx >> 3, c8 = idx & 7;
            uint32_t doff = (uint32_t)nn * ROWPADB + (uint32_t)c8 * 16;
            uint32_t goff = (uint32_t)nn * DIM + (uint32_t)c8 * 8;  // t=0
            cp16(sbase + OFF_B0 + doff, g_w1t + goff);
        }
        cp_commit();
    }
    float4 va[4];                         // A: 512 chunks of 8 floats, 2/thread
#pragma unroll
    for (int u = 0; u < 2; u++) {
        int idx = tid + u * 256;
        int r = idx >> 3, c8 = idx & 7;
        const float4* src = reinterpret_cast<const float4*>(
            x + (size_t)(rowBase + r) * DIM + c8 * 8);
        va[2 * u]     = __ldg(src);
        va[2 * u + 1] = __ldg(src + 1);
    }

    for (int t = 0; t < 8; t++) {
        if (t > 0) __syncthreads();      // B-buffer reads of t-1 done

        // --- convert prefetched A (fp32 -> fp16) into resident slice t
#pragma unroll
        for (int u = 0; u < 2; u++) {
            int idx = tid + u * 256;
            int r = idx >> 3, c8 = idx & 7;
            float f[8] = {va[2 * u].x, va[2 * u].y, va[2 * u].z, va[2 * u].w,
                          va[2 * u + 1].x, va[2 * u + 1].y, va[2 * u + 1].z, va[2 * u + 1].w};
            uint32_t hp[4];
#pragma unroll
            for (int j = 0; j < 4; j++) {
                __half h0 = __float2half_rn(f[2 * j]);
                __half h1 = __float2half_rn(f[2 * j + 1]);
                hp[j] = (uint32_t)__half_as_ushort(h0) | ((uint32_t)__half_as_ushort(h1) << 16);
            }
            *(uint4*)(bp + OFF_A + (uint32_t)r * ROWA + (uint32_t)t * 128
                      + (uint32_t)c8 * 16) = make_uint4(hp[0], hp[1], hp[2], hp[3]);
        }

        // --- issue B[t+1] cp.async into alternate buffer, wait for B[t]
        if (t < 7) {
            uint32_t bufo = ((t + 1) & 1) ? OFF_B1 : OFF_B0;
#pragma unroll
            for (int u = 0; u < 4; u++) {
                int idx = tid + u * 256;
                int nn = idx >> 3, c8 = idx & 7;
                uint32_t doff = (uint32_t)nn * ROWPADB + (uint32_t)c8 * 16;
                uint32_t goff = (uint32_t)nn * DIM + (uint32_t)(t + 1) * KT + (uint32_t)c8 * 8;
                cp16(sbase + bufo + doff, g_w1t + goff);
            }
            cp_commit();
            cp_wait<1>();
        } else {
            cp_wait<0>();
        }
        __syncthreads();

        // --- prefetch next A tile LDGs (latency hidden behind compute below)
        if (t < 7) {
#pragma unroll
            for (int u = 0; u < 2; u++) {
                int idx = tid + u * 256;
                int r = idx >> 3, c8 = idx & 7;
                const float4* src = reinterpret_cast<const float4*>(
                    x + (size_t)(rowBase + r) * DIM + (t + 1) * KT + c8 * 8);
                va[2 * u]     = __ldg(src);
                va[2 * u + 1] = __ldg(src + 1);
            }
        }

        // --- compute: 4 k-steps of 16
        const uint32_t bA = sbase + ((t & 1) ? OFF_B1 : OFF_B0) + b_lane;
        const uint32_t tko = (uint32_t)t * 128;
#pragma unroll
        for (int ks = 0; ks < 4; ks++) {
            const uint32_t ko = (uint32_t)ks * 32;
            uint32_t a[2][4];
#pragma unroll
            for (int m = 0; m < 2; m++) ldsm_x4(a[m], aA[m] + tko + ko);
#pragma unroll
            for (int ntp = 0; ntp < 2; ntp++) {
                const uint32_t no = (uint32_t)ntp * 16 * ROWPADB + ko;
                uint32_t bh[4];
                ldsm_x4(bh, bA + no);
#pragma unroll
                for (int m = 0; m < 2; m++) {
                    mma_f16(acc[m][2 * ntp],     a[m], bh);
                    mma_f16(acc[m][2 * ntp + 1], a[m], bh + 2);
                }
            }
        }
    }

    // --- epilogue: s = sum_col tanh(h + b1[col]) * W2[col]
    const int grp = lid >> 2;
    float p[2][2] = {{0.f, 0.f}, {0.f, 0.f}};
#pragma unroll
    for (int nt = 0; nt < 4; nt++) {
        int c0 = warp_col * 32 + nt * 8 + tig * 2;
        float b1a = __ldg(b1 + c0),     b1b = __ldg(b1 + c0 + 1);
        float w2a = __ldg(W2 + c0),     w2b = __ldg(W2 + c0 + 1);
#pragma unroll
        for (int m = 0; m < 2; m++) {
            p[m][0] += tanhf(acc[m][nt][0] + b1a) * w2a + tanhf(acc[m][nt][1] + b1b) * w2b;
            p[m][1] += tanhf(acc[m][nt][2] + b1a) * w2a + tanhf(acc[m][nt][3] + b1b) * w2b;
        }
    }
#pragma unroll
    for (int m = 0; m < 2; m++)
#pragma unroll
        for (int r = 0; r < 2; r++) {
            p[m][r] += __shfl_xor_sync(0xFFFFFFFF, p[m][r], 1);
            p[m][r] += __shfl_xor_sync(0xFFFFFFFF, p[m][r], 2);
        }
    if (tig == 0) {
#pragma unroll
        for (int m = 0; m < 2; m++)
#pragma unroll
            for (int r = 0; r < 2; r++) {
                int row = warp_row * 32 + m * 16 + r * 8 + grp;
                red[row * 4 + warp_col] = p[m][r];
            }
    }
    __syncthreads();
    if (tid < 64) {
        float s = red[tid * 4] + red[tid * 4 + 1]
                + red[tid * 4 + 2] + red[tid * 4 + 3] + __ldg(b2);
        e_sm[tid] = expf(s);             // no shift needed: |s| <= ~9
    }
    __syncthreads();

    // --- scatter-pool: thread owns dims (2*tid, 2*tid+1); rows sorted by seg
    {
        float a0 = 0.f, a1 = 0.f;
        int cur = seg_sm[0];
        for (int r = 0; r < 64; r++) {
            int sg = seg_sm[r];
            if (sg != cur) {
                atomicAdd(&g_num[(size_t)cur * DIM + 2 * tid],     a0);
                atomicAdd(&g_num[(size_t)cur * DIM + 2 * tid + 1], a1);
                a0 = 0.f; a1 = 0.f; cur = sg;
            }
            float e = e_sm[r];
            float2 f = __half22float2(*reinterpret_cast<const __half2*>(
                bp + OFF_A + (uint32_t)r * ROWA + (uint32_t)tid * 4));
            a0 += e * f.x;
            a1 += e * f.y;
        }
        atomicAdd(&g_num[(size_t)cur * DIM + 2 * tid],     a0);
        atomicAdd(&g_num[(size_t)cur * DIM + 2 * tid + 1], a1);
    }
    if (tid == 0) {
        float d = 0.f;
        int cur = seg_sm[0];
        for (int r = 0; r < 64; r++) {
            int sg = seg_sm[r];
            if (sg != cur) { atomicAdd(&g_den[cur], d); d = 0.f; cur = sg; }
            d += e_sm[r];
        }
        atomicAdd(&g_den[cur], d);
    }
}

// ---------------------------------------------------------------------------
// Kernel 2 (finalize): out[b, d] = num[b, d] / (den[b] + 1e-8)
// ---------------------------------------------------------------------------
__global__ __launch_bounds__(256)
void finalize_kernel(float* __restrict__ out)
{
    const int b = blockIdx.x;
    const int tid = threadIdx.x;
    const float inv = 1.f / (g_den[b] + 1e-8f);
    float2 v = reinterpret_cast<const float2*>(g_num + (size_t)b * DIM)[tid];
    reinterpret_cast<float2*>(out + (size_t)b * DIM)[tid] =
        make_float2(v.x * inv, v.y * inv);
}

// ---------------------------------------------------------------------------
extern "C" void kernel_launch(void* const* d_in, const int* in_sizes, int n_in,
                              void* d_out, int out_size)
{
    const float* x     = (const float*)d_in[0];
    const void*  batch = (const void*)d_in[1];
    const float* W1    = (const float*)d_in[2];
    const float* b1    = (const float*)d_in[3];
    const float* W2    = (const float*)d_in[4];
    const float* b2    = (const float*)d_in[5];
    float*       out   = (float*)d_out;

    const int n = in_sizes[1];
    const int Bseg = out_size / DIM;

    cudaFuncSetAttribute(score_pool_kernel,
                         cudaFuncAttributeMaxDynamicSharedMemorySize, SMEM_REQ);

    prep_kernel<<<4 + ZBLK, 256>>>(Bseg, W1);
    score_pool_kernel<<<n / 64, 256, SMEM_REQ>>>(x, batch, n, b1, W2, b2);
    finalize_kernel<<<Bseg, 256>>>(out);
}

// round 13
// speedup vs baseline: 1.1032x; 1.0857x over previous
#include <cuda_runtime.h>
#include <cuda_bf16.h>
#include <cuda_fp16.h>
#include <cstdint>

// Problem constants (AttentionPool: N=262144, D=512, H=128, B=1024)
#define MAXN 262144
#define MAXB 4096
#define DIM 512
#define HID 128

// ---------------------------------------------------------------------------
// Scratch (allocation-free rule: __device__ globals)
// ---------------------------------------------------------------------------
__device__ __align__(16) float g_num[(size_t)MAXB * DIM];   // 8 MB
__device__ float g_den[MAXB];
// W1^T as fp16, layout [n][k]: n=0..127 rows, k=0..511 contiguous
__device__ __align__(16) unsigned short g_w1t[HID * DIM];

// ---------------------------------------------------------------------------
// Kernel 0 (fused prep):
//  blocks 0..3  : W1^T fp16 transpose via smem (coalesced both sides)
//  blocks 4..131: zero g_num[0..Bseg*DIM) and g_den[0..Bseg)
// ---------------------------------------------------------------------------
#define TPAD 132   // halfs per smem tile row
#define ZBLK 128

__global__ __launch_bounds__(256)
void prep_kernel(int Bseg, const float* __restrict__ W1)
{
    __shared__ unsigned short tile[128][TPAD];
    const int tid = threadIdx.x;

    if (blockIdx.x < 4) {
        const int k0 = blockIdx.x * 128;
#pragma unroll
        for (int u = 0; u < 16; u++) {
            int idx = tid + u * 256;
            int kr = idx >> 5;
            int c4 = idx & 31;
            float4 v = __ldg(reinterpret_cast<const float4*>(
                W1 + (size_t)(k0 + kr) * HID + c4 * 4));
            tile[c4 * 4 + 0][kr] = __half_as_ushort(__float2half_rn(v.x));
            tile[c4 * 4 + 1][kr] = __half_as_ushort(__float2half_rn(v.y));
            tile[c4 * 4 + 2][kr] = __half_as_ushort(__float2half_rn(v.z));
            tile[c4 * 4 + 3][kr] = __half_as_ushort(__float2half_rn(v.w));
        }
        __syncthreads();
#pragma unroll
        for (int u = 0; u < 8; u++) {
            int idx = tid + u * 256;
            int nn = idx >> 4;
            int c8 = idx & 15;
            unsigned short h[8];
#pragma unroll
            for (int j = 0; j < 8; j++) h[j] = tile[nn][c8 * 8 + j];
            *reinterpret_cast<uint4*>(g_w1t + (size_t)nn * DIM + k0 + c8 * 8) =
                *reinterpret_cast<const uint4*>(h);
        }
        return;
    }

    // --- zero accumulators
    const int gid = (blockIdx.x - 4) * 256 + tid;     // ZBLK*256 threads
    const int tot4 = Bseg * (DIM / 4);                // float4 count
    const uint4 z = make_uint4(0, 0, 0, 0);
    for (int i = gid; i < tot4; i += ZBLK * 256)
        reinterpret_cast<uint4*>(g_num)[i] = z;
    if (gid < Bseg) g_den[gid] = 0.f;
}

// ---------------------------------------------------------------------------
// PTX helpers (all sm_80+ baseline -> safe for compute_103 target)
// ---------------------------------------------------------------------------
__device__ __forceinline__ void mma_f16(float* d, const uint32_t* a, const uint32_t* b)
{
    asm volatile(
        "mma.sync.aligned.m16n8k16.row.col.f32.f16.f16.f32 "
        "{%0,%1,%2,%3}, {%4,%5,%6,%7}, {%8,%9}, {%0,%1,%2,%3};"
        : "+f"(d[0]), "+f"(d[1]), "+f"(d[2]), "+f"(d[3])
        : "r"(a[0]), "r"(a[1]), "r"(a[2]), "r"(a[3]), "r"(b[0]), "r"(b[1]));
}
__device__ __forceinline__ void ldsm_x4(uint32_t* r, uint32_t addr)
{
    asm volatile("ldmatrix.sync.aligned.m8n8.x4.shared.b16 {%0,%1,%2,%3}, [%4];"
                 : "=r"(r[0]), "=r"(r[1]), "=r"(r[2]), "=r"(r[3]) : "r"(addr));
}
__device__ __forceinline__ void cp16(uint32_t dst, const void* src)
{
    asm volatile("cp.async.cg.shared.global [%0], [%1], 16;"
                 :: "r"(dst), "l"(src) : "memory");
}
__device__ __forceinline__ void cp_commit()
{
    asm volatile("cp.async.commit_group;" ::: "memory");
}
template <int N>
__device__ __forceinline__ void cp_wait()
{
    asm volatile("cp.async.wait_group %0;" :: "n"(N) : "memory");
}
__device__ __forceinline__ uint32_t smem_u32(const void* p)
{
    uint32_t a;
    asm("{ .reg .u64 t; cvta.to.shared.u64 t, %1; cvt.u32.u64 %0, t; }" : "=r"(a) : "l"(p));
    return a;
}

// ---------------------------------------------------------------------------
// Kernel 1 (fused score + scatter-pool), 128-row frame (R8-measured GEMM):
//   s = tanh(x @ W1 + b1) @ W2 + b2     (single-pass fp16 mma)
// then e_i = exp(s_i) and the block RE-READS its own x tile (L2-hot) to do
//   num[seg] += e_i * x_i,  den[seg] += e_i    via low-contention atomics.
// Block: 128 rows x 128 cols, 8 warps 4x2 (warp tile 32x64), K: 8 tiles of 64.
// 144B-padded smem rows -> conflict-free ldmatrix. B double-buffered cp.async.
// ---------------------------------------------------------------------------
#define KT       64
#define ROWPADB  144                      // bytes per smem row
#define TILE_B   (128 * ROWPADB)          // 18432 bytes per tile buffer
#define OFF_A    0
#define OFF_B0   (1 * TILE_B)
#define OFF_B1   (2 * TILE_B)
#define OFF_TAIL (3 * TILE_B)
// tail: seg[128] ints | e[128] floats | red[128*2] floats
#define OFF_SEG  OFF_TAIL
#define OFF_E    (OFF_TAIL + 512)
#define OFF_RED  (OFF_TAIL + 1024)
#define SMEM_REQ (OFF_TAIL + 2048)        // 57344 B

__global__ __launch_bounds__(256, 2)
void score_pool_kernel(const float* __restrict__ x,
                       const void* __restrict__ batch, int n,
                       const float* __restrict__ b1,
                       const float* __restrict__ W2,
                       const float* __restrict__ b2)
{
    extern __shared__ char bp[];
    const uint32_t sbase = smem_u32(bp);

    const int tid = threadIdx.x;
    const int wid = tid >> 5;
    const int lid = tid & 31;
    const int tig = lid & 3;             // 0..3
    const int warp_row = wid & 3;        // rows warp_row*32 ..
    const int warp_col = wid >> 2;       // cols warp_col*64 ..
    const int rowBase = blockIdx.x * 128;

    int*   seg_sm = (int*)(bp + OFF_SEG);
    float* e_sm   = (float*)(bp + OFF_E);
    float* red    = (float*)(bp + OFF_RED);

    // --- load segment ids for this block's rows
    if (tid < 128) {
        const int i32 = (__ldg((const int*)batch + (n - 1)) != 0);
        seg_sm[tid] = i32 ? __ldg((const int*)batch + rowBase + tid)
                          : (int)__ldg((const long long*)batch + rowBase + tid);
    }

    // ldmatrix per-lane addresses
    const uint32_t a_rl    = (uint32_t)(lid & 15);
    const uint32_t a_chalf = (uint32_t)((lid >> 4) * 16);
    uint32_t aA[2];
#pragma unroll
    for (int m = 0; m < 2; m++) {
        uint32_t row = (uint32_t)(warp_row * 32 + m * 16) + a_rl;
        aA[m] = sbase + OFF_A + row * ROWPADB + a_chalf;
    }
    const uint32_t b_lane = ((uint32_t)(lid & 7) + (uint32_t)((lid >> 4) & 1) * 8) * ROWPADB
                          + (uint32_t)((lid >> 3) & 1) * 16
                          + (uint32_t)warp_col * 64 * ROWPADB;

    float acc[2][8][4];
#pragma unroll
    for (int m = 0; m < 2; m++)
#pragma unroll
        for (int nt = 0; nt < 8; nt++)
#pragma unroll
            for (int j = 0; j < 4; j++) acc[m][nt][j] = 0.f;

    // --- prologue: B[0] via cp.async; A[0] LDGs into registers
    {
#pragma unroll
        for (int u = 0; u < 4; u++) {
            int idx = tid + u * 256;
            int nn = idx >> 3, c8 = idx & 7;
            uint32_t doff = (uint32_t)nn * ROWPADB + (uint32_t)c8 * 16;
            uint32_t goff = (uint32_t)nn * DIM + (uint32_t)c8 * 8;  // t=0
            cp16(sbase + OFF_B0 + doff, g_w1t + goff);
        }
        cp_commit();
    }
    float4 va[8];
#pragma unroll
    for (int u = 0; u < 4; u++) {
        int idx = tid + u * 256;
        int r = idx >> 3, c8 = idx & 7;
        const float4* src = reinterpret_cast<const float4*>(
            x + (size_t)(rowBase + r) * DIM + c8 * 8);
        va[2 * u]     = __ldg(src);
        va[2 * u + 1] = __ldg(src + 1);
    }

    for (int t = 0; t < 8; t++) {
        if (t > 0) __syncthreads();      // prior tile reads done before overwrite

        // --- convert prefetched A (fp32 -> fp16): store to smem
#pragma unroll
        for (int u = 0; u < 4; u++) {
            int idx = tid + u * 256;
            int r = idx >> 3, c8 = idx & 7;
            float f[8] = {va[2 * u].x, va[2 * u].y, va[2 * u].z, va[2 * u].w,
                          va[2 * u + 1].x, va[2 * u + 1].y, va[2 * u + 1].z, va[2 * u + 1].w};
            uint32_t hp[4];
#pragma unroll
            for (int j = 0; j < 4; j++) {
                __half h0 = __float2half_rn(f[2 * j]);
                __half h1 = __float2half_rn(f[2 * j + 1]);
                hp[j] = (uint32_t)__half_as_ushort(h0) | ((uint32_t)__half_as_ushort(h1) << 16);
            }
            uint32_t off = (uint32_t)r * ROWPADB + (uint32_t)c8 * 16;
            *(uint4*)(bp + OFF_A + off) = make_uint4(hp[0], hp[1], hp[2], hp[3]);
        }

        // --- issue B[t+1] cp.async into alternate buffer, wait for B[t]
        if (t < 7) {
            uint32_t bufo = ((t + 1) & 1) ? OFF_B1 : OFF_B0;
#pragma unroll
            for (int u = 0; u < 4; u++) {
                int idx = tid + u * 256;
                int nn = idx >> 3, c8 = idx & 7;
                uint32_t doff = (uint32_t)nn * ROWPADB + (uint32_t)c8 * 16;
                uint32_t goff = (uint32_t)nn * DIM + (uint32_t)(t + 1) * KT + (uint32_t)c8 * 8;
                cp16(sbase + bufo + doff, g_w1t + goff);
            }
            cp_commit();
            cp_wait<1>();                 // B[t] complete; B[t+1] may stay in flight
        } else {
            cp_wait<0>();
        }
        __syncthreads();

        // --- prefetch next A tile LDGs (latency hidden behind compute below)
        if (t < 7) {
#pragma unroll
            for (int u = 0; u < 4; u++) {
                int idx = tid + u * 256;
                int r = idx >> 3, c8 = idx & 7;
                const float4* src = reinterpret_cast<const float4*>(
                    x + (size_t)(rowBase + r) * DIM + (t + 1) * KT + c8 * 8);
                va[2 * u]     = __ldg(src);
                va[2 * u + 1] = __ldg(src + 1);
            }
        }

        // --- compute: 4 k-steps of 16, single pass
        const uint32_t bA = sbase + ((t & 1) ? OFF_B1 : OFF_B0) + b_lane;
#pragma unroll
        for (int ks = 0; ks < 4; ks++) {
            const uint32_t ko = (uint32_t)ks * 32;
            uint32_t a[2][4];
#pragma unroll
            for (int m = 0; m < 2; m++) ldsm_x4(a[m], aA[m] + ko);
#pragma unroll
            for (int ntp = 0; ntp < 4; ntp++) {
                const uint32_t no = (uint32_t)ntp * 16 * ROWPADB + ko;
                uint32_t bh[4];
                ldsm_x4(bh, bA + no);
#pragma unroll
                for (int m = 0; m < 2; m++) {
                    mma_f16(acc[m][2 * ntp],     a[m], bh);
                    mma_f16(acc[m][2 * ntp + 1], a[m], bh + 2);
                }
            }
        }
    }

    // --- epilogue: s = sum_col tanh(h + b1[col]) * W2[col], register-resident
    const int grp = lid >> 2;
    float p[2][2] = {{0.f, 0.f}, {0.f, 0.f}};
#pragma unroll
    for (int nt = 0; nt < 8; nt++) {
        int c0 = warp_col * 64 + nt * 8 + tig * 2;
        float b1a = __ldg(b1 + c0),     b1b = __ldg(b1 + c0 + 1);
        float w2a = __ldg(W2 + c0),     w2b = __ldg(W2 + c0 + 1);
#pragma unroll
        for (int m = 0; m < 2; m++) {
            p[m][0] += tanhf(acc[m][nt][0] + b1a) * w2a + tanhf(acc[m][nt][1] + b1b) * w2b;
            p[m][1] += tanhf(acc[m][nt][2] + b1a) * w2a + tanhf(acc[m][nt][3] + b1b) * w2b;
        }
    }
#pragma unroll
    for (int m = 0; m < 2; m++)
#pragma unroll
        for (int r = 0; r < 2; r++) {
            p[m][r] += __shfl_xor_sync(0xFFFFFFFF, p[m][r], 1);
            p[m][r] += __shfl_xor_sync(0xFFFFFFFF, p[m][r], 2);
        }
    if (tig == 0) {
#pragma unroll
        for (int m = 0; m < 2; m++)
#pragma unroll
            for (int r = 0; r < 2; r++) {
                int row = warp_row * 32 + m * 16 + r * 8 + grp;
                red[row * 2 + warp_col] = p[m][r];
            }
    }
    __syncthreads();
    if (tid < 128) {
        float s = red[tid * 2] + red[tid * 2 + 1] + __ldg(b2);
        e_sm[tid] = expf(s);             // no shift needed: |s| <= ~10, fp32-safe
    }
    __syncthreads();

    // --- scatter-pool: re-read this block's x tile (L2-hot).
    // Thread owns dims (2*tid, 2*tid+1); rows sorted by segment -> few flushes.
    {
        const float2* xp = reinterpret_cast<const float2*>(x) + (size_t)rowBase * (DIM / 2) + tid;
        float a0 = 0.f, a1 = 0.f;
        int cur = seg_sm[0];
        for (int r = 0; r < 128; r += 4) {
            float2 v0 = __ldg(xp + (size_t)(r + 0) * (DIM / 2));
            float2 v1 = __ldg(xp + (size_t)(r + 1) * (DIM / 2));
            float2 v2 = __ldg(xp + (size_t)(r + 2) * (DIM / 2));
            float2 v3 = __ldg(xp + (size_t)(r + 3) * (DIM / 2));
            float2 vv[4] = {v0, v1, v2, v3};
#pragma unroll
            for (int j = 0; j < 4; j++) {
                int sg = seg_sm[r + j];
                if (sg != cur) {
                    atomicAdd(&g_num[(size_t)cur * DIM + 2 * tid],     a0);
                    atomicAdd(&g_num[(size_t)cur * DIM + 2 * tid + 1], a1);
                    a0 = 0.f; a1 = 0.f; cur = sg;
                }
                float e = e_sm[r + j];
                a0 += e * vv[j].x;
                a1 += e * vv[j].y;
            }
        }
        atomicAdd(&g_num[(size_t)cur * DIM + 2 * tid],     a0);
        atomicAdd(&g_num[(size_t)cur * DIM + 2 * tid + 1], a1);
    }
    if (tid == 0) {
        float d = 0.f;
        int cur = seg_sm[0];
        for (int r = 0; r < 128; r++) {
            int sg = seg_sm[r];
            if (sg != cur) { atomicAdd(&g_den[cur], d); d = 0.f; cur = sg; }
            d += e_sm[r];
        }
        atomicAdd(&g_den[cur], d);
    }
}

// ---------------------------------------------------------------------------
// Kernel 2 (finalize): out[b, d] = num[b, d] / (den[b] + 1e-8)
// ---------------------------------------------------------------------------
__global__ __launch_bounds__(256)
void finalize_kernel(float* __restrict__ out)
{
    const int b = blockIdx.x;
    const int tid = threadIdx.x;
    const float inv = 1.f / (g_den[b] + 1e-8f);
    float2 v = reinterpret_cast<const float2*>(g_num + (size_t)b * DIM)[tid];
    reinterpret_cast<float2*>(out + (size_t)b * DIM)[tid] =
        make_float2(v.x * inv, v.y * inv);
}

// ---------------------------------------------------------------------------
extern "C" void kernel_launch(void* const* d_in, const int* in_sizes, int n_in,
                              void* d_out, int out_size)
{
    const float* x     = (const float*)d_in[0];
    const void*  batch = (const void*)d_in[1];
    const float* W1    = (const float*)d_in[2];
    const float* b1    = (const float*)d_in[3];
    const float* W2    = (const float*)d_in[4];
    const float* b2    = (const float*)d_in[5];
    float*       out   = (float*)d_out;

    const int n = in_sizes[1];
    const int Bseg = out_size / DIM;

    cudaFuncSetAttribute(score_pool_kernel,
                         cudaFuncAttributeMaxDynamicSharedMemorySize, SMEM_REQ);

    prep_kernel<<<4 + ZBLK, 256>>>(Bseg, W1);
    score_pool_kernel<<<n / 128, 256, SMEM_REQ>>>(x, batch, n, b1, W2, b2);
    finalize_kernel<<<Bseg, 256>>>(out);
}